// round 6
// baseline (speedup 1.0000x reference)
#include <cuda_runtime.h>
#include <cuda_bf16.h>
#include <cuda_fp16.h>
#include <cstdint>

#define DI __device__ __forceinline__

// ---------------- problem constants ----------------
namespace {
constexpr int BB = 4096;        // batch
constexpr int DD = 1024;        // feature dim
constexpr int KK = 3000;        // prototypes
constexpr int KP = 3072;        // padded K (12 * 256)
constexpr int MT = 8192;        // stacked rows (z1 then z2)
constexpr float INV_EPS = 20.0f;   // 1/0.05
constexpr float INV_T   = 10.0f;   // 1/0.1
}

// ---------------- scratch (device globals; no runtime alloc) ----------------
__device__ __nv_bfloat16 g_Abf[(size_t)MT * DD];   // 16.8 MB
__device__ __nv_bfloat16 g_Wbf[(size_t)KP * DD];   // 6.3 MB (rows >= 3000 zero)
__device__ __half        g_S[(size_t)MT * KP];     // 50.3 MB fp16 scores
__device__ float  g_colE[2 * KP];
__device__ float  g_c[2 * KP];
__device__ float  g_v[2 * KP];
__device__ float  g_lse[MT];
__device__ float  g_u[MT];
__device__ double g_loss;

// ---------------- helpers ----------------
DI uint32_t smem_u32(const void* p) {
    uint32_t a;
    asm("{ .reg .u64 t; cvta.to.shared.u64 t, %1; cvt.u32.u64 %0, t; }" : "=r"(a) : "l"(p));
    return a;
}

DI void cp_async16(uint32_t saddr, const void* gptr) {
    asm volatile("cp.async.cg.shared.global [%0], [%1], 16;"
                 :: "r"(saddr), "l"(gptr) : "memory");
}
#define CP_COMMIT()  asm volatile("cp.async.commit_group;" ::: "memory")
#define CP_WAIT(n)   asm volatile("cp.async.wait_group %0;" :: "n"(n) : "memory")

DI void ldsm4(uint32_t& r0, uint32_t& r1, uint32_t& r2, uint32_t& r3, uint32_t a) {
    asm volatile("ldmatrix.sync.aligned.m8n8.x4.shared.b16 {%0,%1,%2,%3}, [%4];"
                 : "=r"(r0), "=r"(r1), "=r"(r2), "=r"(r3) : "r"(a));
}

DI void mma16816(float* d, const uint32_t* a, const uint32_t* b) {
    asm volatile(
        "mma.sync.aligned.m16n8k16.row.col.f32.bf16.bf16.f32 "
        "{%0,%1,%2,%3}, {%4,%5,%6,%7}, {%8,%9}, {%0,%1,%2,%3};"
        : "+f"(d[0]), "+f"(d[1]), "+f"(d[2]), "+f"(d[3])
        : "r"(a[0]), "r"(a[1]), "r"(a[2]), "r"(a[3]), "r"(b[0]), "r"(b[1]));
}

// conflict-free swizzle for 128B-wide rows: chunk ^= row&7
DI uint32_t sw_off(int row, int ch) {
    return (uint32_t)(row * 128 + ((ch ^ (row & 7)) * 16));
}

// ---------------- kernel 0: zero accumulators ----------------
__global__ void k_zero() {
    int idx = blockIdx.x * blockDim.x + threadIdx.x;   // 8192 threads
    if (idx < 2 * KP) { g_colE[idx] = 0.f; g_c[idx] = 0.f; }
    if (idx < MT) g_lse[idx] = 0.f;
    if (idx == 0) g_loss = 0.0;
}

// ---------------- kernel 1: convert z1|z2 -> bf16 stacked ----------------
__global__ void k_convA(const float* __restrict__ z1, const float* __restrict__ z2) {
    int v = blockIdx.x * blockDim.x + threadIdx.x;     // 0..2097151, 4 elems each
    const float* src = (v < 1048576) ? (z1 + 4 * (size_t)v)
                                     : (z2 + 4 * (size_t)(v - 1048576));
    float4 f = *reinterpret_cast<const float4*>(src);
    __nv_bfloat162* dst = reinterpret_cast<__nv_bfloat162*>(&g_Abf[4 * (size_t)v]);
    dst[0] = __floats2bfloat162_rn(f.x, f.y);
    dst[1] = __floats2bfloat162_rn(f.z, f.w);
}

// ---------------- kernel 2: convert W -> bf16, zero-pad rows [3000,3072) ----
__global__ void k_convW(const float* __restrict__ W) {
    int v = blockIdx.x * blockDim.x + threadIdx.x;     // 0..786431, 4 elems each
    int row = v >> 8;
    __nv_bfloat162 lo, hi;
    if (row < KK) {
        float4 f = *reinterpret_cast<const float4*>(W + 4 * (size_t)v);
        lo = __floats2bfloat162_rn(f.x, f.y);
        hi = __floats2bfloat162_rn(f.z, f.w);
    } else {
        lo = __floats2bfloat162_rn(0.f, 0.f);
        hi = lo;
    }
    __nv_bfloat162* dst = reinterpret_cast<__nv_bfloat162*>(&g_Wbf[4 * (size_t)v]);
    dst[0] = lo;
    dst[1] = hi;
}

// ---------------- kernel 3: mma.sync GEMM + fused pass-A epilogue ------------
// grid (12 ntiles, 64 rowtiles), 256 threads (8 warps: 2 (M) x 4 (N)).
// CTA tile 128x256, warp tile 64x64. K chunks of 64 bf16. 2-stage cp.async.
// smem per stage: A 128x64 = 16KB, B 256x64 = 32KB. 2 stages = 96KB.
static constexpr int NK = 16;       // 1024/64 k-chunks
static constexpr int STAGE_BYTES = 49152;
static constexpr int B_OFF = 16384;

__global__ __launch_bounds__(256, 1) void k_gemm() {
    __shared__ __align__(1024) uint8_t sm[2 * STAGE_BYTES];

    const int tid = threadIdx.x;
    const int wid = tid >> 5;
    const int lid = tid & 31;
    const int warp_m = wid >> 2;       // 0..1
    const int warp_n = wid & 3;        // 0..3
    const int ntile = blockIdx.x;
    const int rtile = blockIdx.y;
    const int arow0 = rtile * 128;
    const int brow0 = ntile * 256;

    const uint32_t sbase = smem_u32(sm);

    float acc[4][8][4];
#pragma unroll
    for (int mi = 0; mi < 4; mi++)
#pragma unroll
        for (int ni = 0; ni < 8; ni++)
#pragma unroll
            for (int c = 0; c < 4; c++) acc[mi][ni][c] = 0.f;

    auto issue_loads = [&](int kc, int stage) {
        const uint32_t st = sbase + stage * STAGE_BYTES;
        const int kb0 = kc * 64;
#pragma unroll
        for (int i = 0; i < 4; i++) {           // A: 1024 chunks
            int idx = tid + i * 256;
            int row = idx >> 3;
            int ch  = idx & 7;
            cp_async16(st + sw_off(row, ch),
                       &g_Abf[(size_t)(arow0 + row) * DD + kb0 + ch * 8]);
        }
#pragma unroll
        for (int i = 0; i < 8; i++) {           // B: 2048 chunks
            int idx = tid + i * 256;
            int row = idx >> 3;                 // 0..255
            int ch  = idx & 7;
            cp_async16(st + B_OFF + sw_off(row, ch),
                       &g_Wbf[(size_t)(brow0 + row) * DD + kb0 + ch * 8]);
        }
    };

    issue_loads(0, 0);
    CP_COMMIT();

    // ldmatrix lane address components
    const int a_rowoff = lid & 15;                  // m within 16
    const int a_chsel  = lid >> 4;                  // +1 chunk for k upper half
    const int b_noff   = ((lid >> 4) & 1) * 8 + (lid & 7);
    const int b_khalf  = (lid >> 3) & 1;

#pragma unroll 1
    for (int kc = 0; kc < NK; kc++) {
        CP_WAIT(0);                 // stage kc resident
        __syncthreads();
        if (kc + 1 < NK) issue_loads(kc + 1, (kc + 1) & 1);
        CP_COMMIT();                // unconditional: keeps group indices aligned

        const uint32_t Ab = sbase + (kc & 1) * STAGE_BYTES;
        const uint32_t Bb = Ab + B_OFF;

#pragma unroll
        for (int ks = 0; ks < 4; ks++) {            // k16 steps within chunk
            uint32_t a[4][4];
            const int chA = ks * 2 + a_chsel;       // logical 16B chunk (0..7)
#pragma unroll
            for (int mi = 0; mi < 4; mi++) {
                int row = warp_m * 64 + mi * 16 + a_rowoff;
                ldsm4(a[mi][0], a[mi][1], a[mi][2], a[mi][3], Ab + sw_off(row, chA));
            }
            uint32_t b[8][2];
            const int chB = ks * 2 + b_khalf;
#pragma unroll
            for (int p = 0; p < 4; p++) {
                int row = warp_n * 64 + p * 16 + b_noff;
                uint32_t r0, r1, r2, r3;
                ldsm4(r0, r1, r2, r3, Bb + sw_off(row, chB));
                b[2 * p][0] = r0; b[2 * p][1] = r1;
                b[2 * p + 1][0] = r2; b[2 * p + 1][1] = r3;
            }
#pragma unroll
            for (int mi = 0; mi < 4; mi++)
#pragma unroll
                for (int ni = 0; ni < 8; ni++)
                    mma16816(acc[mi][ni], a[mi], b[ni]);
        }
    }
    __syncthreads();   // all ldmatrix done before smem reuse below

    // ---- epilogue: fp16 store + pass-A sums ----
    const int g = lid >> 2;      // row group 0..7
    const int t = lid & 3;       // col pair 0..3
    const int m = (arow0 >= BB) ? 1 : 0;

    float* colAcc = reinterpret_cast<float*>(sm);   // 256 floats, reuse smem
    colAcc[tid] = 0.f;
    __syncthreads();

    float colSum[8][2];   // [ni][which col of the pair]
#pragma unroll
    for (int ni = 0; ni < 8; ni++) { colSum[ni][0] = 0.f; colSum[ni][1] = 0.f; }

#pragma unroll
    for (int mi = 0; mi < 4; mi++) {
        const int r0 = arow0 + warp_m * 64 + mi * 16 + g;
        const int r1 = r0 + 8;
        float lse0 = 0.f, lse1 = 0.f;
#pragma unroll
        for (int ni = 0; ni < 8; ni++) {
            const int cl = warp_n * 64 + ni * 8 + 2 * t;   // local col
            const int gc = brow0 + cl;
            const float* c = acc[mi][ni];
            __half2 h01 = __floats2half2_rn(c[0], c[1]);
            __half2 h23 = __floats2half2_rn(c[2], c[3]);
            *reinterpret_cast<__half2*>(&g_S[(size_t)r0 * KP + gc]) = h01;
            *reinterpret_cast<__half2*>(&g_S[(size_t)r1 * KP + gc]) = h23;
            const bool m0 = (gc + 0) < KK;
            const bool m1 = (gc + 1) < KK;
            float e00 = m0 ? __expf(c[0] * INV_EPS) : 0.f;
            float e01 = m1 ? __expf(c[1] * INV_EPS) : 0.f;
            float e10 = m0 ? __expf(c[2] * INV_EPS) : 0.f;
            float e11 = m1 ? __expf(c[3] * INV_EPS) : 0.f;
            colSum[ni][0] += e00 + e10;
            colSum[ni][1] += e01 + e11;
            lse0 += (m0 ? __expf(c[0] * INV_T) : 0.f) + (m1 ? __expf(c[1] * INV_T) : 0.f);
            lse1 += (m0 ? __expf(c[2] * INV_T) : 0.f) + (m1 ? __expf(c[3] * INV_T) : 0.f);
        }
#pragma unroll
        for (int o = 1; o < 4; o <<= 1) {
            lse0 += __shfl_xor_sync(0xffffffffu, lse0, o);
            lse1 += __shfl_xor_sync(0xffffffffu, lse1, o);
        }
        if (t == 0) {
            atomicAdd(&g_lse[r0], lse0);
            atomicAdd(&g_lse[r1], lse1);
        }
    }
#pragma unroll
    for (int ni = 0; ni < 8; ni++) {
#pragma unroll
        for (int o = 4; o < 32; o <<= 1) {
            colSum[ni][0] += __shfl_xor_sync(0xffffffffu, colSum[ni][0], o);
            colSum[ni][1] += __shfl_xor_sync(0xffffffffu, colSum[ni][1], o);
        }
        if (g == 0) {
            const int cl = warp_n * 64 + ni * 8 + 2 * t;
            atomicAdd(&colAcc[cl],     colSum[ni][0]);
            atomicAdd(&colAcc[cl + 1], colSum[ni][1]);
        }
    }
    __syncthreads();
    {
        int col = brow0 + tid;
        if (col < KK) atomicAdd(&g_colE[m * KP + col], colAcc[tid]);
    }
}

// ---------------- kernel 4: finish pass A -> initial v ----------------
__global__ __launch_bounds__(1024) void k_finishA() {
    __shared__ float sred[32];
    __shared__ float sS;
    const int mm = blockIdx.x;
    float acc = 0.f;
    for (int j = threadIdx.x; j < KK; j += 1024) acc += g_colE[mm * KP + j];
#pragma unroll
    for (int o = 16; o > 0; o >>= 1) acc += __shfl_xor_sync(0xffffffffu, acc, o);
    if ((threadIdx.x & 31) == 0) sred[threadIdx.x >> 5] = acc;
    __syncthreads();
    if (threadIdx.x == 0) {
        float tt = 0.f;
#pragma unroll
        for (int w = 0; w < 32; w++) tt += sred[w];
        sS = tt;
    }
    __syncthreads();
    const float S = sS;
    for (int j = threadIdx.x; j < KP; j += 1024)
        g_v[mm * KP + j] = (j < KK) ? S / (3000.0f * g_colE[mm * KP + j]) : 0.0f;
}

// ---------------- kernel 5: row pass -> u (vectorized) ----------------
__global__ __launch_bounds__(128) void k_row() {
    __shared__ float sred[4];
    const int i = blockIdx.x;                       // 0..8191
    const int mm = (i >= BB) ? 1 : 0;
    const uint4* row = reinterpret_cast<const uint4*>(&g_S[(size_t)i * KP]);  // 384 u4
    const float4* v4 = reinterpret_cast<const float4*>(&g_v[mm * KP]);
    float acc = 0.f;
#pragma unroll
    for (int it = 0; it < 3; it++) {
        int jp = threadIdx.x + it * 128;            // 0..383
        uint4 pk = row[jp];
        float4 va = v4[2 * jp], vb = v4[2 * jp + 1];
        float2 s0 = __half22float2(*reinterpret_cast<__half2*>(&pk.x));
        float2 s1 = __half22float2(*reinterpret_cast<__half2*>(&pk.y));
        float2 s2 = __half22float2(*reinterpret_cast<__half2*>(&pk.z));
        float2 s3 = __half22float2(*reinterpret_cast<__half2*>(&pk.w));
        acc += __expf(s0.x * INV_EPS) * va.x + __expf(s0.y * INV_EPS) * va.y
             + __expf(s1.x * INV_EPS) * va.z + __expf(s1.y * INV_EPS) * va.w
             + __expf(s2.x * INV_EPS) * vb.x + __expf(s2.y * INV_EPS) * vb.y
             + __expf(s3.x * INV_EPS) * vb.z + __expf(s3.y * INV_EPS) * vb.w;
    }
#pragma unroll
    for (int o = 16; o > 0; o >>= 1) acc += __shfl_xor_sync(0xffffffffu, acc, o);
    if ((threadIdx.x & 31) == 0) sred[threadIdx.x >> 5] = acc;
    __syncthreads();
    if (threadIdx.x == 0) {
        float tt = sred[0] + sred[1] + sred[2] + sred[3];
        g_u[i] = 1.0f / (4096.0f * tt);
    }
}

// ---------------- kernel 6: col pass -> partial c (atomic) ----------------
__global__ __launch_bounds__(256) void k_col() {
    __shared__ float sacc[256];
    const int ntile = blockIdx.x;                   // 0..23
    const int rchunk = blockIdx.y;                  // 0..63
    const int col = ntile * 128 + (threadIdx.x & 127);
    const int rhalf = threadIdx.x >> 7;
    const int row0 = rchunk * 128;
    const int mm = (row0 >= BB) ? 1 : 0;
    float acc = 0.f;
    if (col < KK) {
#pragma unroll 4
        for (int r = rhalf; r < 128; r += 2) {
            int row = row0 + r;
            float s = __half2float(g_S[(size_t)row * KP + col]);
            acc += __expf(s * INV_EPS) * g_u[row];
        }
    }
    sacc[threadIdx.x] = acc;
    __syncthreads();
    if (threadIdx.x < 128 && col < KK)
        atomicAdd(&g_c[mm * KP + col], sacc[threadIdx.x] + sacc[threadIdx.x + 128]);
}

// ---------------- kernel 7: finish col pass -> v, reset c ----------------
__global__ __launch_bounds__(1024) void k_finishC() {
    int idx = blockIdx.x * blockDim.x + threadIdx.x;
    if (idx < 2 * KP) {
        int j = idx % KP;
        float c = g_c[idx];
        g_v[idx] = (j < KK) ? 1.0f / (3000.0f * c) : 0.0f;
        g_c[idx] = 0.f;
    }
}

// ---------------- kernel 8: loss (fused with final row pass, vectorized) ----
__global__ __launch_bounds__(128) void k_loss() {
    __shared__ float sr1[4], sr2[4], sq1[4], sq2[4];
    const int i = blockIdx.x;                       // 0..4095
    const uint4* r1 = reinterpret_cast<const uint4*>(&g_S[(size_t)i * KP]);
    const uint4* r2 = reinterpret_cast<const uint4*>(&g_S[(size_t)(i + BB) * KP]);
    const float4* v1 = reinterpret_cast<const float4*>(&g_v[0]);
    const float4* v2 = reinterpret_cast<const float4*>(&g_v[KP]);
    float a1 = 0.f, a2 = 0.f;      // sum E v s_other
    float q1 = 0.f, q2 = 0.f;      // row sums sum E v
#pragma unroll
    for (int it = 0; it < 3; it++) {
        int jp = threadIdx.x + it * 128;            // 0..383
        uint4 p1 = r1[jp];
        uint4 p2 = r2[jp];
        float4 v1a = v1[2 * jp], v1b = v1[2 * jp + 1];
        float4 v2a = v2[2 * jp], v2b = v2[2 * jp + 1];
        float s1v[8], s2v[8];
        {
            float2 f;
            f = __half22float2(*reinterpret_cast<__half2*>(&p1.x)); s1v[0]=f.x; s1v[1]=f.y;
            f = __half22float2(*reinterpret_cast<__half2*>(&p1.y)); s1v[2]=f.x; s1v[3]=f.y;
            f = __half22float2(*reinterpret_cast<__half2*>(&p1.z)); s1v[4]=f.x; s1v[5]=f.y;
            f = __half22float2(*reinterpret_cast<__half2*>(&p1.w)); s1v[6]=f.x; s1v[7]=f.y;
            f = __half22float2(*reinterpret_cast<__half2*>(&p2.x)); s2v[0]=f.x; s2v[1]=f.y;
            f = __half22float2(*reinterpret_cast<__half2*>(&p2.y)); s2v[2]=f.x; s2v[3]=f.y;
            f = __half22float2(*reinterpret_cast<__half2*>(&p2.z)); s2v[4]=f.x; s2v[5]=f.y;
            f = __half22float2(*reinterpret_cast<__half2*>(&p2.w)); s2v[6]=f.x; s2v[7]=f.y;
        }
        const float* vv1 = &v1a.x;   // v1a,v1b contiguous in regs? use explicit array
        float v1arr[8] = {v1a.x, v1a.y, v1a.z, v1a.w, v1b.x, v1b.y, v1b.z, v1b.w};
        float v2arr[8] = {v2a.x, v2a.y, v2a.z, v2a.w, v2b.x, v2b.y, v2b.z, v2b.w};
        (void)vv1;
#pragma unroll
        for (int e = 0; e < 8; e++) {
            float w1 = __expf(s1v[e] * INV_EPS) * v1arr[e];
            float w2 = __expf(s2v[e] * INV_EPS) * v2arr[e];
            a2 += w2 * s1v[e];
            a1 += w1 * s2v[e];
            q1 += w1;
            q2 += w2;
        }
    }
#pragma unroll
    for (int o = 16; o > 0; o >>= 1) {
        a1 += __shfl_xor_sync(0xffffffffu, a1, o);
        a2 += __shfl_xor_sync(0xffffffffu, a2, o);
        q1 += __shfl_xor_sync(0xffffffffu, q1, o);
        q2 += __shfl_xor_sync(0xffffffffu, q2, o);
    }
    if ((threadIdx.x & 31) == 0) {
        sr1[threadIdx.x >> 5] = a1;
        sr2[threadIdx.x >> 5] = a2;
        sq1[threadIdx.x >> 5] = q1;
        sq2[threadIdx.x >> 5] = q2;
    }
    __syncthreads();
    if (threadIdx.x == 0) {
        float t1 = sr1[0] + sr1[1] + sr1[2] + sr1[3];
        float t2 = sr2[0] + sr2[1] + sr2[2] + sr2[3];
        float rr1 = sq1[0] + sq1[1] + sq1[2] + sq1[3];
        float rr2 = sq2[0] + sq2[1] + sq2[2] + sq2[3];
        float u1 = 1.0f / (4096.0f * rr1);
        float u2 = 1.0f / (4096.0f * rr2);
        float lse1 = logf(g_lse[i]);
        float lse2 = logf(g_lse[i + BB]);
        float contrib = u2 * t2 * INV_T - lse1 * (1.0f / BB)
                      + u1 * t1 * INV_T - lse2 * (1.0f / BB);
        atomicAdd(&g_loss, (double)contrib);
    }
}

// ---------------- kernel 9: finalize ----------------
__global__ void k_final(float* out) {
    out[0] = (float)(-g_loss * (1.0 / (2.0 * BB)));
}

// ---------------- launch ----------------
extern "C" void kernel_launch(void* const* d_in, const int* in_sizes, int n_in,
                              void* d_out, int out_size) {
    (void)in_sizes; (void)n_in; (void)out_size;
    const float* z1 = (const float*)d_in[0];
    const float* z2 = (const float*)d_in[1];
    const float* W  = (const float*)d_in[2];
    float* out = (float*)d_out;

    k_zero<<<32, 256>>>();
    k_convA<<<8192, 256>>>(z1, z2);
    k_convW<<<3072, 256>>>(W);
    k_gemm<<<dim3(12, 64), 256>>>();
    k_finishA<<<2, 1024>>>();
    // sinkhorn iter 1 (col step folded into GEMM epilogue): row
    k_row<<<8192, 128>>>();
    // iter 2: col, row
    k_col<<<dim3(24, 64), 256>>>();
    k_finishC<<<6, 1024>>>();
    k_row<<<8192, 128>>>();
    // iter 3: col (row fused into loss)
    k_col<<<dim3(24, 64), 256>>>();
    k_finishC<<<6, 1024>>>();
    // loss (includes 3rd row pass)
    k_loss<<<4096, 128>>>();
    k_final<<<1, 1>>>(out);
}

// round 7
// speedup vs baseline: 1.2731x; 1.2731x over previous
#include <cuda_runtime.h>
#include <cuda_bf16.h>
#include <cuda_fp16.h>
#include <cstdint>

#define DI __device__ __forceinline__

// ---------------- problem constants ----------------
namespace {
constexpr int BB = 4096;        // batch
constexpr int DD = 1024;        // feature dim
constexpr int KK = 3000;        // prototypes
constexpr int KP = 3072;        // padded K
constexpr int MT = 8192;        // stacked rows (z1 then z2)
constexpr float INV_EPS = 20.0f;   // 1/0.05
constexpr float INV_T   = 10.0f;   // 1/0.1
}

// ---------------- scratch (device globals; no runtime alloc) ----------------
__device__ __nv_bfloat16 g_Abf[(size_t)MT * DD];   // 16.8 MB
__device__ __nv_bfloat16 g_Wbf[(size_t)KP * DD];   // 6.3 MB (rows >= 3000 zero)
__device__ __half        g_S[(size_t)MT * KP];     // 50.3 MB fp16 scores
__device__ float  g_colE[2 * KP];
__device__ float  g_c[2 * KP];
__device__ float  g_v[2 * KP];
__device__ float  g_lse[MT];
__device__ float  g_u[MT];
__device__ double g_loss;

// ---------------- helpers ----------------
DI uint32_t smem_u32(const void* p) {
    uint32_t a;
    asm("{ .reg .u64 t; cvta.to.shared.u64 t, %1; cvt.u32.u64 %0, t; }" : "=r"(a) : "l"(p));
    return a;
}

DI void cp_async16(uint32_t saddr, const void* gptr) {
    asm volatile("cp.async.cg.shared.global [%0], [%1], 16;"
                 :: "r"(saddr), "l"(gptr) : "memory");
}
#define CP_COMMIT()  asm volatile("cp.async.commit_group;" ::: "memory")
#define CP_WAIT(n)   asm volatile("cp.async.wait_group %0;" :: "n"(n) : "memory")

DI void ldsm4(uint32_t& r0, uint32_t& r1, uint32_t& r2, uint32_t& r3, uint32_t a) {
    asm volatile("ldmatrix.sync.aligned.m8n8.x4.shared.b16 {%0,%1,%2,%3}, [%4];"
                 : "=r"(r0), "=r"(r1), "=r"(r2), "=r"(r3) : "r"(a));
}

DI void mma16816(float* d, const uint32_t* a, const uint32_t* b) {
    asm volatile(
        "mma.sync.aligned.m16n8k16.row.col.f32.bf16.bf16.f32 "
        "{%0,%1,%2,%3}, {%4,%5,%6,%7}, {%8,%9}, {%0,%1,%2,%3};"
        : "+f"(d[0]), "+f"(d[1]), "+f"(d[2]), "+f"(d[3])
        : "r"(a[0]), "r"(a[1]), "r"(a[2]), "r"(a[3]), "r"(b[0]), "r"(b[1]));
}

// conflict-free swizzle for 128B-wide rows: chunk ^= row&7
DI uint32_t sw_off(int row, int ch) {
    return (uint32_t)(row * 128 + ((ch ^ (row & 7)) * 16));
}

// ---------------- kernel 0: zero accumulators ----------------
__global__ void k_zero() {
    int idx = blockIdx.x * blockDim.x + threadIdx.x;   // 8192 threads
    if (idx < 2 * KP) { g_colE[idx] = 0.f; g_c[idx] = 0.f; }
    if (idx < MT) g_lse[idx] = 0.f;
    if (idx == 0) g_loss = 0.0;
}

// ---------------- kernel 1: convert z1|z2 -> bf16 stacked ----------------
__global__ void k_convA(const float* __restrict__ z1, const float* __restrict__ z2) {
    int v = blockIdx.x * blockDim.x + threadIdx.x;     // 0..2097151, 4 elems each
    const float* src = (v < 1048576) ? (z1 + 4 * (size_t)v)
                                     : (z2 + 4 * (size_t)(v - 1048576));
    float4 f = *reinterpret_cast<const float4*>(src);
    __nv_bfloat162* dst = reinterpret_cast<__nv_bfloat162*>(&g_Abf[4 * (size_t)v]);
    dst[0] = __floats2bfloat162_rn(f.x, f.y);
    dst[1] = __floats2bfloat162_rn(f.z, f.w);
}

// ---------------- kernel 2: convert W -> bf16, zero-pad rows [3000,3072) ----
__global__ void k_convW(const float* __restrict__ W) {
    int v = blockIdx.x * blockDim.x + threadIdx.x;     // 0..786431, 4 elems each
    int row = v >> 8;
    __nv_bfloat162 lo, hi;
    if (row < KK) {
        float4 f = *reinterpret_cast<const float4*>(W + 4 * (size_t)v);
        lo = __floats2bfloat162_rn(f.x, f.y);
        hi = __floats2bfloat162_rn(f.z, f.w);
    } else {
        lo = __floats2bfloat162_rn(0.f, 0.f);
        hi = lo;
    }
    __nv_bfloat162* dst = reinterpret_cast<__nv_bfloat162*>(&g_Wbf[4 * (size_t)v]);
    dst[0] = lo;
    dst[1] = hi;
}

// ---------------- kernel 3: mma.sync GEMM + fused pass-A epilogue ------------
// grid (24 ntiles, 64 rowtiles), 256 threads (8 warps: 2 (M) x 4 (N)).
// CTA tile 128x128, K chunks of 64 bf16. 3-stage cp.async pipeline. 2 CTAs/SM.
static constexpr int NK = 16;       // 1024/64 k-chunks
static constexpr int STAGES = 3;
static constexpr int STAGE_BYTES = 32768;

__global__ __launch_bounds__(256, 2) void k_gemm() {
    __shared__ __align__(1024) uint8_t sm[STAGES * STAGE_BYTES];

    const int tid = threadIdx.x;
    const int wid = tid >> 5;
    const int lid = tid & 31;
    const int warp_m = wid >> 2;       // 0..1
    const int warp_n = wid & 3;        // 0..3
    const int ntile = blockIdx.x;
    const int rtile = blockIdx.y;
    const int arow0 = rtile * 128;
    const int brow0 = ntile * 128;

    const uint32_t sbase = smem_u32(sm);

    float acc[4][4][4];
#pragma unroll
    for (int mi = 0; mi < 4; mi++)
#pragma unroll
        for (int ni = 0; ni < 4; ni++)
#pragma unroll
            for (int c = 0; c < 4; c++) acc[mi][ni][c] = 0.f;

    auto issue_loads = [&](int kc, int stage) {
        const uint32_t st = sbase + stage * STAGE_BYTES;
#pragma unroll
        for (int i = 0; i < 4; i++) {
            int idx = tid + i * 256;        // 0..1023
            int row = idx >> 3;             // 0..127
            int ch  = idx & 7;              // 16B chunk in 128B row
            int kb  = kc * 64 + ch * 8;     // element offset in k
            uint32_t so = sw_off(row, ch);
            cp_async16(st + so,         &g_Abf[(size_t)(arow0 + row) * DD + kb]);
            cp_async16(st + 16384 + so, &g_Wbf[(size_t)(brow0 + row) * DD + kb]);
        }
    };

    // prologue: fill 2 stages
#pragma unroll
    for (int s = 0; s < STAGES - 1; s++) {
        issue_loads(s, s);
        CP_COMMIT();
    }

    // ldmatrix lane address components
    const int a_rowoff = lid & 15;                  // m within 16
    const int a_chsel  = lid >> 4;                  // +1 chunk for k upper half
    const int b_noff   = ((lid >> 4) & 1) * 8 + (lid & 7);
    const int b_khalf  = (lid >> 3) & 1;

    int stage = 0;
#pragma unroll 1
    for (int kc = 0; kc < NK; kc++) {
        CP_WAIT(1);                 // stage kc resident
        __syncthreads();
        if (kc + STAGES - 1 < NK) {
            int ns = stage + (STAGES - 1);
            if (ns >= STAGES) ns -= STAGES;
            issue_loads(kc + STAGES - 1, ns);
        }
        CP_COMMIT();                // unconditional: keeps group indices aligned

        const uint32_t Ab = sbase + stage * STAGE_BYTES;
        const uint32_t Bb = Ab + 16384;
        stage = (stage + 1 == STAGES) ? 0 : stage + 1;

#pragma unroll
        for (int ks = 0; ks < 4; ks++) {            // k16 steps within chunk
            uint32_t a[4][4];
            const int chA = ks * 2 + a_chsel;       // logical 16B chunk (0..7)
#pragma unroll
            for (int mi = 0; mi < 4; mi++) {
                int row = warp_m * 64 + mi * 16 + a_rowoff;
                ldsm4(a[mi][0], a[mi][1], a[mi][2], a[mi][3], Ab + sw_off(row, chA));
            }
            uint32_t b[4][2];
            const int chB = ks * 2 + b_khalf;
#pragma unroll
            for (int p = 0; p < 2; p++) {
                int row = warp_n * 32 + p * 16 + b_noff;
                uint32_t r0, r1, r2, r3;
                ldsm4(r0, r1, r2, r3, Bb + sw_off(row, chB));
                b[2 * p][0] = r0; b[2 * p][1] = r1;
                b[2 * p + 1][0] = r2; b[2 * p + 1][1] = r3;
            }
#pragma unroll
            for (int mi = 0; mi < 4; mi++)
#pragma unroll
                for (int ni = 0; ni < 4; ni++)
                    mma16816(acc[mi][ni], a[mi], b[ni]);
        }
    }
    __syncthreads();   // all ldmatrix done before smem reuse below

    // ---- epilogue: fp16 store + pass-A sums ----
    const int g = lid >> 2;      // row group 0..7
    const int t = lid & 3;       // col pair 0..3
    const int m = (arow0 >= BB) ? 1 : 0;

    float* colAcc = reinterpret_cast<float*>(sm);   // 128 floats, reuse smem
    if (tid < 128) colAcc[tid] = 0.f;
    __syncthreads();

    float colSum[4][2];   // [ni][which col of the pair]
#pragma unroll
    for (int ni = 0; ni < 4; ni++) { colSum[ni][0] = 0.f; colSum[ni][1] = 0.f; }

#pragma unroll
    for (int mi = 0; mi < 4; mi++) {
        const int r0 = arow0 + warp_m * 64 + mi * 16 + g;
        const int r1 = r0 + 8;
        float lse0 = 0.f, lse1 = 0.f;
#pragma unroll
        for (int ni = 0; ni < 4; ni++) {
            const int cl = warp_n * 32 + ni * 8 + 2 * t;   // local col
            const int gc = brow0 + cl;
            const float* c = acc[mi][ni];
            __half2 h01 = __floats2half2_rn(c[0], c[1]);
            __half2 h23 = __floats2half2_rn(c[2], c[3]);
            *reinterpret_cast<__half2*>(&g_S[(size_t)r0 * KP + gc]) = h01;
            *reinterpret_cast<__half2*>(&g_S[(size_t)r1 * KP + gc]) = h23;
            const bool m0 = (gc + 0) < KK;
            const bool m1 = (gc + 1) < KK;
            float e00 = m0 ? __expf(c[0] * INV_EPS) : 0.f;
            float e01 = m1 ? __expf(c[1] * INV_EPS) : 0.f;
            float e10 = m0 ? __expf(c[2] * INV_EPS) : 0.f;
            float e11 = m1 ? __expf(c[3] * INV_EPS) : 0.f;
            colSum[ni][0] += e00 + e10;
            colSum[ni][1] += e01 + e11;
            lse0 += (m0 ? __expf(c[0] * INV_T) : 0.f) + (m1 ? __expf(c[1] * INV_T) : 0.f);
            lse1 += (m0 ? __expf(c[2] * INV_T) : 0.f) + (m1 ? __expf(c[3] * INV_T) : 0.f);
        }
#pragma unroll
        for (int o = 1; o < 4; o <<= 1) {
            lse0 += __shfl_xor_sync(0xffffffffu, lse0, o);
            lse1 += __shfl_xor_sync(0xffffffffu, lse1, o);
        }
        if (t == 0) {
            atomicAdd(&g_lse[r0], lse0);
            atomicAdd(&g_lse[r1], lse1);
        }
    }
#pragma unroll
    for (int ni = 0; ni < 4; ni++) {
#pragma unroll
        for (int o = 4; o < 32; o <<= 1) {
            colSum[ni][0] += __shfl_xor_sync(0xffffffffu, colSum[ni][0], o);
            colSum[ni][1] += __shfl_xor_sync(0xffffffffu, colSum[ni][1], o);
        }
        if (g == 0) {
            const int cl = warp_n * 32 + ni * 8 + 2 * t;
            atomicAdd(&colAcc[cl],     colSum[ni][0]);
            atomicAdd(&colAcc[cl + 1], colSum[ni][1]);
        }
    }
    __syncthreads();
    if (tid < 128) {
        int col = brow0 + tid;
        if (col < KK) atomicAdd(&g_colE[m * KP + col], colAcc[tid]);
    }
}

// ---------------- kernel 4: finish pass A -> initial v ----------------
__global__ __launch_bounds__(1024) void k_finishA() {
    __shared__ float sred[32];
    __shared__ float sS;
    const int mm = blockIdx.x;
    float acc = 0.f;
    for (int j = threadIdx.x; j < KK; j += 1024) acc += g_colE[mm * KP + j];
#pragma unroll
    for (int o = 16; o > 0; o >>= 1) acc += __shfl_xor_sync(0xffffffffu, acc, o);
    if ((threadIdx.x & 31) == 0) sred[threadIdx.x >> 5] = acc;
    __syncthreads();
    if (threadIdx.x == 0) {
        float tt = 0.f;
#pragma unroll
        for (int w = 0; w < 32; w++) tt += sred[w];
        sS = tt;
    }
    __syncthreads();
    const float S = sS;
    for (int j = threadIdx.x; j < KP; j += 1024)
        g_v[mm * KP + j] = (j < KK) ? S / (3000.0f * g_colE[mm * KP + j]) : 0.0f;
}

// ---------------- kernel 5: row pass -> u (vectorized) ----------------
__global__ __launch_bounds__(128) void k_row() {
    __shared__ float sred[4];
    const int i = blockIdx.x;                       // 0..8191
    const int mm = (i >= BB) ? 1 : 0;
    const uint4* row = reinterpret_cast<const uint4*>(&g_S[(size_t)i * KP]);  // 384 u4
    const float4* v4 = reinterpret_cast<const float4*>(&g_v[mm * KP]);
    float acc = 0.f;
#pragma unroll
    for (int it = 0; it < 3; it++) {
        int jp = threadIdx.x + it * 128;            // 0..383
        uint4 pk = row[jp];
        float4 va = v4[2 * jp], vb = v4[2 * jp + 1];
        float2 s0 = __half22float2(*reinterpret_cast<__half2*>(&pk.x));
        float2 s1 = __half22float2(*reinterpret_cast<__half2*>(&pk.y));
        float2 s2 = __half22float2(*reinterpret_cast<__half2*>(&pk.z));
        float2 s3 = __half22float2(*reinterpret_cast<__half2*>(&pk.w));
        acc += __expf(s0.x * INV_EPS) * va.x + __expf(s0.y * INV_EPS) * va.y
             + __expf(s1.x * INV_EPS) * va.z + __expf(s1.y * INV_EPS) * va.w
             + __expf(s2.x * INV_EPS) * vb.x + __expf(s2.y * INV_EPS) * vb.y
             + __expf(s3.x * INV_EPS) * vb.z + __expf(s3.y * INV_EPS) * vb.w;
    }
#pragma unroll
    for (int o = 16; o > 0; o >>= 1) acc += __shfl_xor_sync(0xffffffffu, acc, o);
    if ((threadIdx.x & 31) == 0) sred[threadIdx.x >> 5] = acc;
    __syncthreads();
    if (threadIdx.x == 0) {
        float tt = sred[0] + sred[1] + sred[2] + sred[3];
        g_u[i] = 1.0f / (4096.0f * tt);
    }
}

// ---------------- kernel 6: col pass -> partial c (vectorized) --------------
// grid (12, 32), 256 threads. Block covers 256 cols x 256 rows.
// Warp = one row at a time (broadcast u); thread owns 8 consecutive cols.
__global__ __launch_bounds__(256) void k_col() {
    __shared__ float sacc[8][256];    // [warp][cg + 32*e] bank-conflict-free writes
    const int cg = threadIdx.x & 31;        // col group within 256-col block
    const int wr = threadIdx.x >> 5;        // warp id 0..7
    const int c0 = blockIdx.x * 256 + cg * 8;
    const int row0 = blockIdx.y * 256;
    const int mm = (row0 >= BB) ? 1 : 0;

    float acc[8];
#pragma unroll
    for (int e = 0; e < 8; e++) acc[e] = 0.f;

#pragma unroll 4
    for (int r = row0 + wr; r < row0 + 256; r += 8) {
        uint4 pk = *reinterpret_cast<const uint4*>(&g_S[(size_t)r * KP + c0]);
        float u = g_u[r];
        float2 f0 = __half22float2(*reinterpret_cast<__half2*>(&pk.x));
        float2 f1 = __half22float2(*reinterpret_cast<__half2*>(&pk.y));
        float2 f2 = __half22float2(*reinterpret_cast<__half2*>(&pk.z));
        float2 f3 = __half22float2(*reinterpret_cast<__half2*>(&pk.w));
        acc[0] += __expf(f0.x * INV_EPS) * u;
        acc[1] += __expf(f0.y * INV_EPS) * u;
        acc[2] += __expf(f1.x * INV_EPS) * u;
        acc[3] += __expf(f1.y * INV_EPS) * u;
        acc[4] += __expf(f2.x * INV_EPS) * u;
        acc[5] += __expf(f2.y * INV_EPS) * u;
        acc[6] += __expf(f3.x * INV_EPS) * u;
        acc[7] += __expf(f3.y * INV_EPS) * u;
    }
#pragma unroll
    for (int e = 0; e < 8; e++) sacc[wr][cg + 32 * e] = acc[e];
    __syncthreads();

    // thread tid reduces one column: local col c = tid, stored at [w][c/8 + 32*(c%8)]
    const int c = threadIdx.x;
    const int col = blockIdx.x * 256 + c;
    if (col < KK) {
        const int sidx = (c >> 3) + 32 * (c & 7);
        float s = 0.f;
#pragma unroll
        for (int w = 0; w < 8; w++) s += sacc[w][sidx];
        atomicAdd(&g_c[mm * KP + col], s);
    }
}

// ---------------- kernel 7: finish col pass -> v, reset c ----------------
__global__ __launch_bounds__(1024) void k_finishC() {
    int idx = blockIdx.x * blockDim.x + threadIdx.x;
    if (idx < 2 * KP) {
        int j = idx % KP;
        float c = g_c[idx];
        g_v[idx] = (j < KK) ? 1.0f / (3000.0f * c) : 0.0f;
        g_c[idx] = 0.f;
    }
}

// ---------------- kernel 8: loss (fused with final row pass, vectorized) ----
__global__ __launch_bounds__(128) void k_loss() {
    __shared__ float sr1[4], sr2[4], sq1[4], sq2[4];
    const int i = blockIdx.x;                       // 0..4095
    const uint4* r1 = reinterpret_cast<const uint4*>(&g_S[(size_t)i * KP]);
    const uint4* r2 = reinterpret_cast<const uint4*>(&g_S[(size_t)(i + BB) * KP]);
    const float4* v1 = reinterpret_cast<const float4*>(&g_v[0]);
    const float4* v2 = reinterpret_cast<const float4*>(&g_v[KP]);
    float a1 = 0.f, a2 = 0.f;      // sum E v s_other
    float q1 = 0.f, q2 = 0.f;      // row sums sum E v
#pragma unroll
    for (int it = 0; it < 3; it++) {
        int jp = threadIdx.x + it * 128;            // 0..383
        uint4 p1 = r1[jp];
        uint4 p2 = r2[jp];
        float4 v1a = v1[2 * jp], v1b = v1[2 * jp + 1];
        float4 v2a = v2[2 * jp], v2b = v2[2 * jp + 1];
        float s1v[8], s2v[8];
        {
            float2 f;
            f = __half22float2(*reinterpret_cast<__half2*>(&p1.x)); s1v[0]=f.x; s1v[1]=f.y;
            f = __half22float2(*reinterpret_cast<__half2*>(&p1.y)); s1v[2]=f.x; s1v[3]=f.y;
            f = __half22float2(*reinterpret_cast<__half2*>(&p1.z)); s1v[4]=f.x; s1v[5]=f.y;
            f = __half22float2(*reinterpret_cast<__half2*>(&p1.w)); s1v[6]=f.x; s1v[7]=f.y;
            f = __half22float2(*reinterpret_cast<__half2*>(&p2.x)); s2v[0]=f.x; s2v[1]=f.y;
            f = __half22float2(*reinterpret_cast<__half2*>(&p2.y)); s2v[2]=f.x; s2v[3]=f.y;
            f = __half22float2(*reinterpret_cast<__half2*>(&p2.z)); s2v[4]=f.x; s2v[5]=f.y;
            f = __half22float2(*reinterpret_cast<__half2*>(&p2.w)); s2v[6]=f.x; s2v[7]=f.y;
        }
        float v1arr[8] = {v1a.x, v1a.y, v1a.z, v1a.w, v1b.x, v1b.y, v1b.z, v1b.w};
        float v2arr[8] = {v2a.x, v2a.y, v2a.z, v2a.w, v2b.x, v2b.y, v2b.z, v2b.w};
#pragma unroll
        for (int e = 0; e < 8; e++) {
            float w1 = __expf(s1v[e] * INV_EPS) * v1arr[e];
            float w2 = __expf(s2v[e] * INV_EPS) * v2arr[e];
            a2 += w2 * s1v[e];
            a1 += w1 * s2v[e];
            q1 += w1;
            q2 += w2;
        }
    }
#pragma unroll
    for (int o = 16; o > 0; o >>= 1) {
        a1 += __shfl_xor_sync(0xffffffffu, a1, o);
        a2 += __shfl_xor_sync(0xffffffffu, a2, o);
        q1 += __shfl_xor_sync(0xffffffffu, q1, o);
        q2 += __shfl_xor_sync(0xffffffffu, q2, o);
    }
    if ((threadIdx.x & 31) == 0) {
        sr1[threadIdx.x >> 5] = a1;
        sr2[threadIdx.x >> 5] = a2;
        sq1[threadIdx.x >> 5] = q1;
        sq2[threadIdx.x >> 5] = q2;
    }
    __syncthreads();
    if (threadIdx.x == 0) {
        float t1 = sr1[0] + sr1[1] + sr1[2] + sr1[3];
        float t2 = sr2[0] + sr2[1] + sr2[2] + sr2[3];
        float rr1 = sq1[0] + sq1[1] + sq1[2] + sq1[3];
        float rr2 = sq2[0] + sq2[1] + sq2[2] + sq2[3];
        float u1 = 1.0f / (4096.0f * rr1);
        float u2 = 1.0f / (4096.0f * rr2);
        float lse1 = logf(g_lse[i]);
        float lse2 = logf(g_lse[i + BB]);
        float contrib = u2 * t2 * INV_T - lse1 * (1.0f / BB)
                      + u1 * t1 * INV_T - lse2 * (1.0f / BB);
        atomicAdd(&g_loss, (double)contrib);
    }
}

// ---------------- kernel 9: finalize ----------------
__global__ void k_final(float* out) {
    out[0] = (float)(-g_loss * (1.0 / (2.0 * BB)));
}

// ---------------- launch ----------------
extern "C" void kernel_launch(void* const* d_in, const int* in_sizes, int n_in,
                              void* d_out, int out_size) {
    (void)in_sizes; (void)n_in; (void)out_size;
    const float* z1 = (const float*)d_in[0];
    const float* z2 = (const float*)d_in[1];
    const float* W  = (const float*)d_in[2];
    float* out = (float*)d_out;

    k_zero<<<32, 256>>>();
    k_convA<<<8192, 256>>>(z1, z2);
    k_convW<<<3072, 256>>>(W);
    k_gemm<<<dim3(24, 64), 256>>>();
    k_finishA<<<2, 1024>>>();
    // sinkhorn iter 1 (col step folded into GEMM epilogue): row
    k_row<<<8192, 128>>>();
    // iter 2: col, row
    k_col<<<dim3(12, 32), 256>>>();
    k_finishC<<<6, 1024>>>();
    k_row<<<8192, 128>>>();
    // iter 3: col (row fused into loss)
    k_col<<<dim3(12, 32), 256>>>();
    k_finishC<<<6, 1024>>>();
    // loss (includes 3rd row pass)
    k_loss<<<4096, 128>>>();
    k_final<<<1, 1>>>(out);
}